// round 2
// baseline (speedup 1.0000x reference)
#include <cuda_runtime.h>

// ---------------------------------------------------------------------------
// Shapes (fixed by the problem)
// ---------------------------------------------------------------------------
#define BT   12          // B*T
#define CF   1024        // fused channels
#define CQ   128         // q/k channels
#define NTOK 2401        // 49*49 tokens
#define NP   2432        // padded tokens = 19*128
#define HF   49

// ---------------------------------------------------------------------------
// Scratch (device globals — allocation inside kernel_launch is forbidden)
// ---------------------------------------------------------------------------
__device__ float g_X  [(size_t)BT * CF * NP];   // fused input  [bt][c][n]
__device__ float g_Q  [(size_t)BT * CQ * NP];   // q            [bt][o][n]
__device__ float g_K  [(size_t)BT * CQ * NP];   // k            [bt][o][n]
__device__ float g_V  [(size_t)BT * CF * NP];   // v            [bt][c][n]
__device__ float g_ATT[(size_t)BT * NP * NP];   // scores/probs [bt][n][m]

// ---------------------------------------------------------------------------
// 1) Build fused feature map x[bt][c][n], zero-padded for n in [2401,2432)
//    c<512 : tac[bt][c][i/7][j/7], c>=512 : img[bt][c-512][i%7][j%7]
// ---------------------------------------------------------------------------
__global__ void build_x_kernel(const float* __restrict__ img,
                               const float* __restrict__ tac) {
    int n  = blockIdx.x * 256 + threadIdx.x;
    int c  = blockIdx.y;
    int bt = blockIdx.z;
    if (n >= NP) return;
    float v = 0.0f;
    if (n < NTOK) {
        int i = n / HF, j = n % HF;
        if (c < 512)
            v = tac[(((size_t)bt * 512 + c) * 7 + (i / 7)) * 7 + (j / 7)];
        else
            v = img[(((size_t)bt * 512 + (c - 512)) * 7 + (i % 7)) * 7 + (j % 7)];
    }
    g_X[((size_t)bt * CF + c) * NP + n] = v;
}

// ---------------------------------------------------------------------------
// 2) Y[m][n] = sum_c W[m][c] * X[c][n] + b[m]      (per bt)
//    W: [M x 1024] row-major.  BM=BN=128, BK=8, 256 thr, 8x8/thread.
// ---------------------------------------------------------------------------
__global__ __launch_bounds__(256, 2)
void gemm_wx_kernel(const float* __restrict__ W,
                    const float* __restrict__ bias,
                    float* __restrict__ Y, int M) {
    __shared__ float As[8][128];
    __shared__ float Bs[8][128];

    const int bt = blockIdx.z;
    const float* X  = g_X + (size_t)bt * CF * NP;
    float*       Yb = Y   + (size_t)bt * M  * NP;

    const int n0 = blockIdx.x * 128;
    const int m0 = blockIdx.y * 128;
    const int t  = threadIdx.x;
    const int tx = t & 15;          // 0..15 -> n
    const int ty = t >> 4;          // 0..15 -> m

    const int a_row = t >> 1;            // 0..127
    const int a_k   = (t & 1) * 4;       // 0 or 4
    const int b_k   = t >> 5;            // 0..7
    const int b_n   = (t & 31) * 4;      // 0..124

    float acc[8][8];
    #pragma unroll
    for (int i = 0; i < 8; i++)
        #pragma unroll
        for (int j = 0; j < 8; j++) acc[i][j] = 0.0f;

    for (int k0 = 0; k0 < 1024; k0 += 8) {
        float4 av = *reinterpret_cast<const float4*>(
            &W[(size_t)(m0 + a_row) * 1024 + k0 + a_k]);
        As[a_k + 0][a_row] = av.x;
        As[a_k + 1][a_row] = av.y;
        As[a_k + 2][a_row] = av.z;
        As[a_k + 3][a_row] = av.w;
        float4 bvv = *reinterpret_cast<const float4*>(
            &X[(size_t)(k0 + b_k) * NP + n0 + b_n]);
        *reinterpret_cast<float4*>(&Bs[b_k][b_n]) = bvv;
        __syncthreads();

        #pragma unroll
        for (int k = 0; k < 8; k++) {
            float ar[8], br[8];
            *reinterpret_cast<float4*>(&ar[0]) = *reinterpret_cast<const float4*>(&As[k][ty * 8]);
            *reinterpret_cast<float4*>(&ar[4]) = *reinterpret_cast<const float4*>(&As[k][ty * 8 + 4]);
            *reinterpret_cast<float4*>(&br[0]) = *reinterpret_cast<const float4*>(&Bs[k][tx * 8]);
            *reinterpret_cast<float4*>(&br[4]) = *reinterpret_cast<const float4*>(&Bs[k][tx * 8 + 4]);
            #pragma unroll
            for (int i = 0; i < 8; i++)
                #pragma unroll
                for (int j = 0; j < 8; j++)
                    acc[i][j] = fmaf(ar[i], br[j], acc[i][j]);
        }
        __syncthreads();
    }

    #pragma unroll
    for (int i = 0; i < 8; i++) {
        int m = m0 + ty * 8 + i;
        float b = bias[m];
        float* yr = &Yb[(size_t)m * NP + n0 + tx * 8];
        #pragma unroll
        for (int j = 0; j < 8; j += 4) {
            float4 o;
            o.x = acc[i][j + 0] + b;
            o.y = acc[i][j + 1] + b;
            o.z = acc[i][j + 2] + b;
            o.w = acc[i][j + 3] + b;
            *reinterpret_cast<float4*>(&yr[j]) = o;
        }
    }
}

// ---------------------------------------------------------------------------
// 3) S[n][m] = sum_o Q[o][n] * K[o][m]   (K-dim = 128), writes raw scores
// ---------------------------------------------------------------------------
__global__ __launch_bounds__(256, 2)
void gemm_score_kernel() {
    __shared__ float As[8][128];   // Q slice: [o][n]
    __shared__ float Bs[8][128];   // K slice: [o][m]

    const int bt = blockIdx.z;
    const float* Qb = g_Q + (size_t)bt * CQ * NP;
    const float* Kb = g_K + (size_t)bt * CQ * NP;
    float*       Sb = g_ATT + (size_t)bt * NP * NP;

    const int n0 = blockIdx.y * 128;
    const int m0 = blockIdx.x * 128;
    const int t  = threadIdx.x;
    const int tx = t & 15;          // -> m
    const int ty = t >> 4;          // -> n

    const int l_o = t >> 5;          // 0..7
    const int l_c = (t & 31) * 4;    // 0..124

    float acc[8][8];
    #pragma unroll
    for (int i = 0; i < 8; i++)
        #pragma unroll
        for (int j = 0; j < 8; j++) acc[i][j] = 0.0f;

    for (int k0 = 0; k0 < CQ; k0 += 8) {
        *reinterpret_cast<float4*>(&As[l_o][l_c]) =
            *reinterpret_cast<const float4*>(&Qb[(size_t)(k0 + l_o) * NP + n0 + l_c]);
        *reinterpret_cast<float4*>(&Bs[l_o][l_c]) =
            *reinterpret_cast<const float4*>(&Kb[(size_t)(k0 + l_o) * NP + m0 + l_c]);
        __syncthreads();

        #pragma unroll
        for (int k = 0; k < 8; k++) {
            float ar[8], br[8];
            *reinterpret_cast<float4*>(&ar[0]) = *reinterpret_cast<const float4*>(&As[k][ty * 8]);
            *reinterpret_cast<float4*>(&ar[4]) = *reinterpret_cast<const float4*>(&As[k][ty * 8 + 4]);
            *reinterpret_cast<float4*>(&br[0]) = *reinterpret_cast<const float4*>(&Bs[k][tx * 8]);
            *reinterpret_cast<float4*>(&br[4]) = *reinterpret_cast<const float4*>(&Bs[k][tx * 8 + 4]);
            #pragma unroll
            for (int i = 0; i < 8; i++)
                #pragma unroll
                for (int j = 0; j < 8; j++)
                    acc[i][j] = fmaf(ar[i], br[j], acc[i][j]);
        }
        __syncthreads();
    }

    #pragma unroll
    for (int i = 0; i < 8; i++) {
        float* sr = &Sb[(size_t)(n0 + ty * 8 + i) * NP + m0 + tx * 8];
        #pragma unroll
        for (int j = 0; j < 8; j += 4) {
            float4 o;
            o.x = acc[i][j + 0]; o.y = acc[i][j + 1];
            o.z = acc[i][j + 2]; o.w = acc[i][j + 3];
            *reinterpret_cast<float4*>(&sr[j]) = o;
        }
    }
}

// ---------------------------------------------------------------------------
// 4) Row softmax over m<2401; zero the padding columns m in [2401,2432)
// ---------------------------------------------------------------------------
__global__ __launch_bounds__(256)
void softmax_kernel() {
    __shared__ float row[NTOK];
    __shared__ float red[256];

    const int n  = blockIdx.x;
    const int bt = blockIdx.y;
    float* base  = g_ATT + ((size_t)bt * NP + n) * NP;
    const int t  = threadIdx.x;

    float mx = -1e30f;
    for (int m = t; m < NTOK; m += 256) {
        float v = base[m];
        row[m] = v;
        mx = fmaxf(mx, v);
    }
    red[t] = mx;
    __syncthreads();
    for (int s = 128; s > 0; s >>= 1) {
        if (t < s) red[t] = fmaxf(red[t], red[t + s]);
        __syncthreads();
    }
    mx = red[0];
    __syncthreads();

    float sum = 0.0f;
    for (int m = t; m < NTOK; m += 256) {
        float e = __expf(row[m] - mx);
        row[m] = e;
        sum += e;
    }
    red[t] = sum;
    __syncthreads();
    for (int s = 128; s > 0; s >>= 1) {
        if (t < s) red[t] += red[t + s];
        __syncthreads();
    }
    float inv = 1.0f / red[0];

    for (int m = t; m < NTOK; m += 256) base[m] = row[m] * inv;
    for (int m = NTOK + t; m < NP; m += 256) base[m] = 0.0f;
}

// ---------------------------------------------------------------------------
// 5) out[c][n] = gamma * sum_m V[c][m] * P[n][m] + X[c][n]
//    K-dim = NP (padding columns of P are zero). Output row stride = 2401.
// ---------------------------------------------------------------------------
__global__ __launch_bounds__(256, 2)
void gemm_out_kernel(const float* __restrict__ gamma,
                     float* __restrict__ out) {
    __shared__ float As[8][128];   // V^T slice: [m][c]
    __shared__ float Bs[8][128];   // P^T slice: [m][n]

    const int bt = blockIdx.z;
    const float* Vb = g_V   + (size_t)bt * CF * NP;
    const float* Pb = g_ATT + (size_t)bt * NP * NP;
    const float* Xb = g_X   + (size_t)bt * CF * NP;
    float*       Ob = out   + (size_t)bt * CF * NTOK;

    const int n0 = blockIdx.x * 128;
    const int c0 = blockIdx.y * 128;
    const int t  = threadIdx.x;
    const int tx = t & 15;          // -> n
    const int ty = t >> 4;          // -> c

    const int l_row = t >> 1;            // 0..127
    const int l_k   = (t & 1) * 4;       // 0 or 4

    float acc[8][8];
    #pragma unroll
    for (int i = 0; i < 8; i++)
        #pragma unroll
        for (int j = 0; j < 8; j++) acc[i][j] = 0.0f;

    for (int k0 = 0; k0 < NP; k0 += 8) {
        float4 av = *reinterpret_cast<const float4*>(
            &Vb[(size_t)(c0 + l_row) * NP + k0 + l_k]);
        As[l_k + 0][l_row] = av.x;
        As[l_k + 1][l_row] = av.y;
        As[l_k + 2][l_row] = av.z;
        As[l_k + 3][l_row] = av.w;
        float4 bvv = *reinterpret_cast<const float4*>(
            &Pb[(size_t)(n0 + l_row) * NP + k0 + l_k]);
        Bs[l_k + 0][l_row] = bvv.x;
        Bs[l_k + 1][l_row] = bvv.y;
        Bs[l_k + 2][l_row] = bvv.z;
        Bs[l_k + 3][l_row] = bvv.w;
        __syncthreads();

        #pragma unroll
        for (int k = 0; k < 8; k++) {
            float ar[8], br[8];
            *reinterpret_cast<float4*>(&ar[0]) = *reinterpret_cast<const float4*>(&As[k][ty * 8]);
            *reinterpret_cast<float4*>(&ar[4]) = *reinterpret_cast<const float4*>(&As[k][ty * 8 + 4]);
            *reinterpret_cast<float4*>(&br[0]) = *reinterpret_cast<const float4*>(&Bs[k][tx * 8]);
            *reinterpret_cast<float4*>(&br[4]) = *reinterpret_cast<const float4*>(&Bs[k][tx * 8 + 4]);
            #pragma unroll
            for (int i = 0; i < 8; i++)
                #pragma unroll
                for (int j = 0; j < 8; j++)
                    acc[i][j] = fmaf(ar[i], br[j], acc[i][j]);
        }
        __syncthreads();
    }

    const float g = __ldg(gamma);
    #pragma unroll
    for (int i = 0; i < 8; i++) {
        int c = c0 + ty * 8 + i;
        const float* xr = &Xb[(size_t)c * NP + n0 + tx * 8];
        float*       orow = &Ob[(size_t)c * NTOK + n0 + tx * 8];
        #pragma unroll
        for (int j = 0; j < 8; j++) {
            int n = n0 + tx * 8 + j;
            if (n < NTOK) orow[j] = g * acc[i][j] + xr[j];
        }
    }
}

// ---------------------------------------------------------------------------
// Launch. Inputs (metadata order):
//   0: x_img [2,6,512,7,7]  1: x_tac [2,6,512,7,7]
//   2: Wq [128,1024]  3: bq [128]  4: Wk [128,1024]  5: bk [128]
//   6: Wv [1024,1024] 7: bv [1024] 8: gamma [1]
// Output: [2,6,1024,49,49] fp32
// ---------------------------------------------------------------------------
extern "C" void kernel_launch(void* const* d_in, const int* in_sizes, int n_in,
                              void* d_out, int out_size) {
    const float* img   = (const float*)d_in[0];
    const float* tac   = (const float*)d_in[1];
    const float* Wq    = (const float*)d_in[2];
    const float* bq    = (const float*)d_in[3];
    const float* Wk    = (const float*)d_in[4];
    const float* bk    = (const float*)d_in[5];
    const float* Wv    = (const float*)d_in[6];
    const float* bv    = (const float*)d_in[7];
    const float* gamma = (const float*)d_in[8];
    float* out = (float*)d_out;

    float* gX;   cudaGetSymbolAddress((void**)&gX,   g_X);
    float* gQ;   cudaGetSymbolAddress((void**)&gQ,   g_Q);
    float* gK;   cudaGetSymbolAddress((void**)&gK,   g_K);
    float* gV;   cudaGetSymbolAddress((void**)&gV,   g_V);

    // 1) fused feature map
    build_x_kernel<<<dim3((NP + 255) / 256, CF, BT), 256>>>(img, tac);

    // 2) q, k, v projections
    gemm_wx_kernel<<<dim3(NP / 128, CQ / 128, BT), 256>>>(Wq, bq, gQ, CQ);
    gemm_wx_kernel<<<dim3(NP / 128, CQ / 128, BT), 256>>>(Wk, bk, gK, CQ);
    gemm_wx_kernel<<<dim3(NP / 128, CF / 128, BT), 256>>>(Wv, bv, gV, CF);

    // 3) attention scores
    gemm_score_kernel<<<dim3(NP / 128, NP / 128, BT), 256>>>();

    // 4) softmax rows
    softmax_kernel<<<dim3(NTOK, BT), 256>>>();

    // 5) out = gamma * V @ P^T + X
    gemm_out_kernel<<<dim3(NP / 128, CF / 128, BT), 256>>>(gamma, out);
}

// round 4
// speedup vs baseline: 1.7167x; 1.7167x over previous
#include <cuda_runtime.h>
#include <cstdint>

// ---------------------------------------------------------------------------
// Shapes
// ---------------------------------------------------------------------------
#define BT   12
#define CF   1024
#define CQ   128
#define NTOK 2401
#define NP   2432
#define HF   49

// ---------------------------------------------------------------------------
// Scratch
// ---------------------------------------------------------------------------
__device__ float g_X  [(size_t)BT * CF * NP];   // [bt][c][n]
__device__ float g_XT [(size_t)BT * NP * CF];   // [bt][n][c]
__device__ float g_Q  [(size_t)BT * CQ * NP];   // [bt][o][n]
__device__ float g_K  [(size_t)BT * CQ * NP];   // [bt][o][n]
__device__ float g_V  [(size_t)BT * CF * NP];   // [bt][c][n]
__device__ float g_ATT[(size_t)BT * NP * NP];   // [bt][n][m]

__device__ __forceinline__ uint32_t f2tf(float f) {
    uint32_t u; asm("cvt.rna.tf32.f32 %0, %1;" : "=r"(u) : "f"(f)); return u;
}

__device__ __forceinline__ void mma_tf32(float c[4], const uint32_t a[4], const uint32_t b[2]) {
    asm volatile(
        "mma.sync.aligned.m16n8k8.row.col.f32.tf32.tf32.f32 "
        "{%0,%1,%2,%3}, {%4,%5,%6,%7}, {%8,%9}, {%0,%1,%2,%3};"
        : "+f"(c[0]), "+f"(c[1]), "+f"(c[2]), "+f"(c[3])
        : "r"(a[0]), "r"(a[1]), "r"(a[2]), "r"(a[3]), "r"(b[0]), "r"(b[1]));
}

// ---------------------------------------------------------------------------
// 1a) X[bt][c][n]  (zero-padded n)
// ---------------------------------------------------------------------------
__global__ void build_x_kernel(const float* __restrict__ img,
                               const float* __restrict__ tac) {
    int n = blockIdx.x * 256 + threadIdx.x;
    int c = blockIdx.y, bt = blockIdx.z;
    if (n >= NP) return;
    float v = 0.0f;
    if (n < NTOK) {
        int i = n / HF, j = n % HF;
        v = (c < 512)
            ? tac[(((size_t)bt * 512 + c) * 7 + (i / 7)) * 7 + (j / 7)]
            : img[(((size_t)bt * 512 + (c - 512)) * 7 + (i % 7)) * 7 + (j % 7)];
    }
    g_X[((size_t)bt * CF + c) * NP + n] = v;
}

// ---------------------------------------------------------------------------
// 1b) XT[bt][n][c]  (zero rows for n >= NTOK)
// ---------------------------------------------------------------------------
__global__ void build_xt_kernel(const float* __restrict__ img,
                                const float* __restrict__ tac) {
    int c = blockIdx.x * 256 + threadIdx.x;
    int n = blockIdx.y, bt = blockIdx.z;
    if (c >= CF) return;
    float v = 0.0f;
    if (n < NTOK) {
        int i = n / HF, j = n % HF;
        v = (c < 512)
            ? tac[(((size_t)bt * 512 + c) * 7 + (i / 7)) * 7 + (j / 7)]
            : img[(((size_t)bt * 512 + (c - 512)) * 7 + (i % 7)) * 7 + (j % 7)];
    }
    g_XT[((size_t)bt * NP + n) * CF + c] = v;
}

// ---------------------------------------------------------------------------
// 2) fp32 SIMT GEMM for q/k
// ---------------------------------------------------------------------------
__global__ __launch_bounds__(256, 2)
void gemm_wx_kernel(const float* __restrict__ W, const float* __restrict__ bias,
                    float* __restrict__ Y, int M) {
    __shared__ float As[8][128];
    __shared__ float Bs[8][128];
    const int bt = blockIdx.z;
    const float* X = g_X + (size_t)bt * CF * NP;
    float* Yb = Y + (size_t)bt * M * NP;
    const int n0 = blockIdx.x * 128, m0 = blockIdx.y * 128;
    const int t = threadIdx.x, tx = t & 15, ty = t >> 4;
    const int a_row = t >> 1, a_k = (t & 1) * 4;
    const int b_k = t >> 5, b_n = (t & 31) * 4;

    float acc[8][8];
    #pragma unroll
    for (int i = 0; i < 8; i++)
        #pragma unroll
        for (int j = 0; j < 8; j++) acc[i][j] = 0.0f;

    for (int k0 = 0; k0 < 1024; k0 += 8) {
        float4 av = *reinterpret_cast<const float4*>(&W[(size_t)(m0 + a_row) * 1024 + k0 + a_k]);
        As[a_k + 0][a_row] = av.x; As[a_k + 1][a_row] = av.y;
        As[a_k + 2][a_row] = av.z; As[a_k + 3][a_row] = av.w;
        *reinterpret_cast<float4*>(&Bs[b_k][b_n]) =
            *reinterpret_cast<const float4*>(&X[(size_t)(k0 + b_k) * NP + n0 + b_n]);
        __syncthreads();
        #pragma unroll
        for (int k = 0; k < 8; k++) {
            float ar[8], br[8];
            *reinterpret_cast<float4*>(&ar[0]) = *reinterpret_cast<const float4*>(&As[k][ty * 8]);
            *reinterpret_cast<float4*>(&ar[4]) = *reinterpret_cast<const float4*>(&As[k][ty * 8 + 4]);
            *reinterpret_cast<float4*>(&br[0]) = *reinterpret_cast<const float4*>(&Bs[k][tx * 8]);
            *reinterpret_cast<float4*>(&br[4]) = *reinterpret_cast<const float4*>(&Bs[k][tx * 8 + 4]);
            #pragma unroll
            for (int i = 0; i < 8; i++)
                #pragma unroll
                for (int j = 0; j < 8; j++) acc[i][j] = fmaf(ar[i], br[j], acc[i][j]);
        }
        __syncthreads();
    }
    #pragma unroll
    for (int i = 0; i < 8; i++) {
        int m = m0 + ty * 8 + i;
        float b = bias[m];
        float* yr = &Yb[(size_t)m * NP + n0 + tx * 8];
        #pragma unroll
        for (int j = 0; j < 8; j += 4) {
            float4 o = { acc[i][j] + b, acc[i][j + 1] + b, acc[i][j + 2] + b, acc[i][j + 3] + b };
            *reinterpret_cast<float4*>(&yr[j]) = o;
        }
    }
}

// ---------------------------------------------------------------------------
// 3) fp32 scores: S[n][m] = sum_o Q[o][n] K[o][m]
// ---------------------------------------------------------------------------
__global__ __launch_bounds__(256, 2)
void gemm_score_kernel() {
    __shared__ float As[8][128];
    __shared__ float Bs[8][128];
    const int bt = blockIdx.z;
    const float* Qb = g_Q + (size_t)bt * CQ * NP;
    const float* Kb = g_K + (size_t)bt * CQ * NP;
    float* Sb = g_ATT + (size_t)bt * NP * NP;
    const int n0 = blockIdx.y * 128, m0 = blockIdx.x * 128;
    const int t = threadIdx.x, tx = t & 15, ty = t >> 4;
    const int l_o = t >> 5, l_c = (t & 31) * 4;

    float acc[8][8];
    #pragma unroll
    for (int i = 0; i < 8; i++)
        #pragma unroll
        for (int j = 0; j < 8; j++) acc[i][j] = 0.0f;

    for (int k0 = 0; k0 < CQ; k0 += 8) {
        *reinterpret_cast<float4*>(&As[l_o][l_c]) =
            *reinterpret_cast<const float4*>(&Qb[(size_t)(k0 + l_o) * NP + n0 + l_c]);
        *reinterpret_cast<float4*>(&Bs[l_o][l_c]) =
            *reinterpret_cast<const float4*>(&Kb[(size_t)(k0 + l_o) * NP + m0 + l_c]);
        __syncthreads();
        #pragma unroll
        for (int k = 0; k < 8; k++) {
            float ar[8], br[8];
            *reinterpret_cast<float4*>(&ar[0]) = *reinterpret_cast<const float4*>(&As[k][ty * 8]);
            *reinterpret_cast<float4*>(&ar[4]) = *reinterpret_cast<const float4*>(&As[k][ty * 8 + 4]);
            *reinterpret_cast<float4*>(&br[0]) = *reinterpret_cast<const float4*>(&Bs[k][tx * 8]);
            *reinterpret_cast<float4*>(&br[4]) = *reinterpret_cast<const float4*>(&Bs[k][tx * 8 + 4]);
            #pragma unroll
            for (int i = 0; i < 8; i++)
                #pragma unroll
                for (int j = 0; j < 8; j++) acc[i][j] = fmaf(ar[i], br[j], acc[i][j]);
        }
        __syncthreads();
    }
    #pragma unroll
    for (int i = 0; i < 8; i++) {
        float* sr = &Sb[(size_t)(n0 + ty * 8 + i) * NP + m0 + tx * 8];
        #pragma unroll
        for (int j = 0; j < 8; j += 4) {
            float4 o = { acc[i][j], acc[i][j + 1], acc[i][j + 2], acc[i][j + 3] };
            *reinterpret_cast<float4*>(&sr[j]) = o;
        }
    }
}

// ---------------------------------------------------------------------------
// 4) row softmax (m < 2401), zero padding columns
// ---------------------------------------------------------------------------
__global__ __launch_bounds__(256)
void softmax_kernel() {
    __shared__ float row[NTOK];
    __shared__ float red[256];
    const int n = blockIdx.x, bt = blockIdx.y;
    float* base = g_ATT + ((size_t)bt * NP + n) * NP;
    const int t = threadIdx.x;

    float mx = -1e30f;
    for (int m = t; m < NTOK; m += 256) { float v = base[m]; row[m] = v; mx = fmaxf(mx, v); }
    red[t] = mx; __syncthreads();
    for (int s = 128; s > 0; s >>= 1) { if (t < s) red[t] = fmaxf(red[t], red[t + s]); __syncthreads(); }
    mx = red[0]; __syncthreads();

    float sum = 0.0f;
    for (int m = t; m < NTOK; m += 256) { float e = __expf(row[m] - mx); row[m] = e; sum += e; }
    red[t] = sum; __syncthreads();
    for (int s = 128; s > 0; s >>= 1) { if (t < s) red[t] += red[t + s]; __syncthreads(); }
    float inv = 1.0f / red[0];

    for (int m = t; m < NTOK; m += 256) base[m] = row[m] * inv;
    for (int m = NTOK + t; m < NP; m += 256) base[m] = 0.0f;
}

// ---------------------------------------------------------------------------
// 5) tf32 mma.sync GEMM: C[M,N], A[M,K] K-major, B[N,K] K-major.
//    Block 128x128, K-chunk 32, 8 warps (2M x 4N), warp tile 64x32.
//    EPI 0: C = acc + bias[m]                 (ldc = NP, all cols)
//    EPI 1: C = gamma*acc + X[m][n], n<NTOK   (ldc = NTOK)
// ---------------------------------------------------------------------------
#define LDS_S 36                     // padded row stride (floats)
#define MMA_SMEM (4 * 128 * LDS_S * 4)   // 73728 bytes (2 bufs x (A+B))

template <int EPI>
__global__ __launch_bounds__(256, 1)
void gemm_mma_kernel(const float* __restrict__ A, int lda, size_t strideA,
                     const float* __restrict__ B, int ldb, size_t strideB,
                     int K,
                     const float* __restrict__ bias,
                     const float* __restrict__ gamma,
                     const float* __restrict__ Xres,
                     float* __restrict__ C, int ldc, size_t strideC) {
    extern __shared__ uint32_t sm[];
    uint32_t* Abuf[2] = { sm,               sm + 2 * 128 * LDS_S };
    uint32_t* Bbuf[2] = { sm + 128 * LDS_S, sm + 3 * 128 * LDS_S };

    const int bt = blockIdx.z;
    const int m0 = blockIdx.x * 128;
    const int n0 = blockIdx.y * 128;
    const float* Ab = A + (size_t)bt * strideA + (size_t)m0 * lda;
    const float* Bb = B + (size_t)bt * strideB + (size_t)n0 * ldb;

    const int t = threadIdx.x;
    const int wid = t >> 5, lane = t & 31;
    const int warp_m = wid & 1, warp_n = wid >> 1;
    const int l4 = lane >> 2, lm = lane & 3;

    // producer mapping: 2 threads per row, 16 floats each
    const int prow = t >> 1;
    const int pcol = (t & 1) * 16;
    const float* aRow = Ab + (size_t)prow * lda + pcol;
    const float* bRow = Bb + (size_t)prow * ldb + pcol;
    const int sOff = prow * LDS_S + pcol;

    float acc[4][4][4];
    #pragma unroll
    for (int mi = 0; mi < 4; mi++)
        #pragma unroll
        for (int ni = 0; ni < 4; ni++)
            #pragma unroll
            for (int r = 0; r < 4; r++) acc[mi][ni][r] = 0.0f;

    const int NCH = K / 32;

    // prologue: load + store chunk 0
    float4 pa[4], pb[4];
    #pragma unroll
    for (int q = 0; q < 4; q++) {
        pa[q] = *reinterpret_cast<const float4*>(aRow + q * 4);
        pb[q] = *reinterpret_cast<const float4*>(bRow + q * 4);
    }
    #pragma unroll
    for (int q = 0; q < 4; q++) {
        uint4 ua = { f2tf(pa[q].x), f2tf(pa[q].y), f2tf(pa[q].z), f2tf(pa[q].w) };
        uint4 ub = { f2tf(pb[q].x), f2tf(pb[q].y), f2tf(pb[q].z), f2tf(pb[q].w) };
        *reinterpret_cast<uint4*>(&Abuf[0][sOff + q * 4]) = ua;
        *reinterpret_cast<uint4*>(&Bbuf[0][sOff + q * 4]) = ub;
    }
    __syncthreads();

    for (int ch = 0; ch < NCH; ch++) {
        const int buf = ch & 1;
        if (ch + 1 < NCH) {
            const int k1 = (ch + 1) * 32;
            #pragma unroll
            for (int q = 0; q < 4; q++) {
                pa[q] = *reinterpret_cast<const float4*>(aRow + k1 + q * 4);
                pb[q] = *reinterpret_cast<const float4*>(bRow + k1 + q * 4);
            }
        }
        const uint32_t* as = Abuf[buf];
        const uint32_t* bs = Bbuf[buf];
        #pragma unroll
        for (int ks = 0; ks < 4; ks++) {
            const int kk = ks * 8;
            uint32_t a[4][4], b[4][2];
            #pragma unroll
            for (int mi = 0; mi < 4; mi++) {
                int base = (warp_m * 64 + mi * 16 + l4) * LDS_S + kk + lm;
                a[mi][0] = as[base];
                a[mi][1] = as[base + 8 * LDS_S];
                a[mi][2] = as[base + 4];
                a[mi][3] = as[base + 8 * LDS_S + 4];
            }
            #pragma unroll
            for (int ni = 0; ni < 4; ni++) {
                int base = (warp_n * 32 + ni * 8 + l4) * LDS_S + kk + lm;
                b[ni][0] = bs[base];
                b[ni][1] = bs[base + 4];
            }
            #pragma unroll
            for (int mi = 0; mi < 4; mi++)
                #pragma unroll
                for (int ni = 0; ni < 4; ni++)
                    mma_tf32(acc[mi][ni], a[mi], b[ni]);
        }
        if (ch + 1 < NCH) {
            uint32_t* an = Abuf[buf ^ 1];
            uint32_t* bn = Bbuf[buf ^ 1];
            #pragma unroll
            for (int q = 0; q < 4; q++) {
                uint4 ua = { f2tf(pa[q].x), f2tf(pa[q].y), f2tf(pa[q].z), f2tf(pa[q].w) };
                uint4 ub = { f2tf(pb[q].x), f2tf(pb[q].y), f2tf(pb[q].z), f2tf(pb[q].w) };
                *reinterpret_cast<uint4*>(&an[sOff + q * 4]) = ua;
                *reinterpret_cast<uint4*>(&bn[sOff + q * 4]) = ub;
            }
        }
        __syncthreads();
    }

    // epilogue
    if (EPI == 0) {
        float* Cb = C + (size_t)bt * strideC;
        #pragma unroll
        for (int mi = 0; mi < 4; mi++) {
            const int gr = m0 + warp_m * 64 + mi * 16 + l4;
            const float bv0 = bias[gr], bv8 = bias[gr + 8];
            #pragma unroll
            for (int ni = 0; ni < 4; ni++) {
                const int gc = n0 + warp_n * 32 + ni * 8 + lm * 2;
                float2 o0 = { acc[mi][ni][0] + bv0, acc[mi][ni][1] + bv0 };
                float2 o1 = { acc[mi][ni][2] + bv8, acc[mi][ni][3] + bv8 };
                *reinterpret_cast<float2*>(&Cb[(size_t)gr * ldc + gc]) = o0;
                *reinterpret_cast<float2*>(&Cb[(size_t)(gr + 8) * ldc + gc]) = o1;
            }
        }
    } else {
        const float g = __ldg(gamma);
        const float* Xb = Xres + (size_t)bt * CF * NP;
        float* Cb = C + (size_t)bt * strideC;
        #pragma unroll
        for (int mi = 0; mi < 4; mi++) {
            const int gr = m0 + warp_m * 64 + mi * 16 + l4;
            #pragma unroll
            for (int ni = 0; ni < 4; ni++) {
                const int gc = n0 + warp_n * 32 + ni * 8 + lm * 2;
                if (gc < NTOK)
                    Cb[(size_t)gr * ldc + gc] = g * acc[mi][ni][0] + Xb[(size_t)gr * NP + gc];
                if (gc + 1 < NTOK)
                    Cb[(size_t)gr * ldc + gc + 1] = g * acc[mi][ni][1] + Xb[(size_t)gr * NP + gc + 1];
                if (gc < NTOK)
                    Cb[(size_t)(gr + 8) * ldc + gc] = g * acc[mi][ni][2] + Xb[(size_t)(gr + 8) * NP + gc];
                if (gc + 1 < NTOK)
                    Cb[(size_t)(gr + 8) * ldc + gc + 1] = g * acc[mi][ni][3] + Xb[(size_t)(gr + 8) * NP + gc + 1];
            }
        }
    }
}

// ---------------------------------------------------------------------------
// Launch
// ---------------------------------------------------------------------------
extern "C" void kernel_launch(void* const* d_in, const int* in_sizes, int n_in,
                              void* d_out, int out_size) {
    const float* img   = (const float*)d_in[0];
    const float* tac   = (const float*)d_in[1];
    const float* Wq    = (const float*)d_in[2];
    const float* bq    = (const float*)d_in[3];
    const float* Wk    = (const float*)d_in[4];
    const float* bk    = (const float*)d_in[5];
    const float* Wv    = (const float*)d_in[6];
    const float* bv    = (const float*)d_in[7];
    const float* gamma = (const float*)d_in[8];
    float* out = (float*)d_out;

    float* gX;  cudaGetSymbolAddress((void**)&gX,  g_X);
    float* gXT; cudaGetSymbolAddress((void**)&gXT, g_XT);
    float* gQ;  cudaGetSymbolAddress((void**)&gQ,  g_Q);
    float* gK;  cudaGetSymbolAddress((void**)&gK,  g_K);
    float* gV;  cudaGetSymbolAddress((void**)&gV,  g_V);
    float* gA;  cudaGetSymbolAddress((void**)&gA,  g_ATT);

    cudaFuncSetAttribute(gemm_mma_kernel<0>, cudaFuncAttributeMaxDynamicSharedMemorySize, MMA_SMEM);
    cudaFuncSetAttribute(gemm_mma_kernel<1>, cudaFuncAttributeMaxDynamicSharedMemorySize, MMA_SMEM);

    // 1) fused feature maps
    build_x_kernel <<<dim3((NP + 255) / 256, CF, BT), 256>>>(img, tac);
    build_xt_kernel<<<dim3(CF / 256, NP, BT), 256>>>(img, tac);

    // 2) q, k projections (fp32 SIMT)
    gemm_wx_kernel<<<dim3(NP / 128, 1, BT), 256>>>(Wq, bq, gQ, CQ);
    gemm_wx_kernel<<<dim3(NP / 128, 1, BT), 256>>>(Wk, bk, gK, CQ);

    // 3) v projection (tf32 mma): V[c][n] = Wv @ XT^T + bv
    gemm_mma_kernel<0><<<dim3(CF / 128, NP / 128, BT), 256, MMA_SMEM>>>(
        Wv, CF, 0,
        gXT, CF, (size_t)NP * CF,
        CF, bv, nullptr, nullptr,
        gV, NP, (size_t)CF * NP);

    // 4) attention scores (fp32 SIMT) + softmax
    gemm_score_kernel<<<dim3(NP / 128, NP / 128, BT), 256>>>();
    softmax_kernel<<<dim3(NTOK, BT), 256>>>();

    // 5) out = gamma * (V @ P^T) + X (tf32 mma)
    gemm_mma_kernel<1><<<dim3(CF / 128, NP / 128, BT), 256, MMA_SMEM>>>(
        gV, NP, (size_t)CF * NP,
        gA, NP, (size_t)NP * NP,
        NP, nullptr, gamma, gX,
        out, NTOK, (size_t)CF * NTOK);
}

// round 5
// speedup vs baseline: 1.7849x; 1.0397x over previous
#include <cuda_runtime.h>
#include <cstdint>

// ---------------------------------------------------------------------------
// Shapes
// ---------------------------------------------------------------------------
#define BT   12
#define CF   1024
#define CQ   128
#define NTOK 2401
#define NP   2432
#define HF   49

// ---------------------------------------------------------------------------
// Scratch
// ---------------------------------------------------------------------------
__device__ float g_X  [(size_t)BT * CF * NP];   // [bt][c][n]
__device__ float g_XT [(size_t)BT * NP * CF];   // [bt][n][c]
__device__ float g_QT [(size_t)BT * NP * CQ];   // [bt][n][o]
__device__ float g_KT [(size_t)BT * NP * CQ];   // [bt][m][o]
__device__ float g_V  [(size_t)BT * CF * NP];   // [bt][c][n]
__device__ float g_ATT[(size_t)BT * NP * NP];   // [bt][n][m]

__device__ __forceinline__ uint32_t f2tf(float f) {
    uint32_t u; asm("cvt.rna.tf32.f32 %0, %1;" : "=r"(u) : "f"(f)); return u;
}

__device__ __forceinline__ void mma_tf32(float c[4], const uint32_t a[4], const uint32_t b[2]) {
    asm volatile(
        "mma.sync.aligned.m16n8k8.row.col.f32.tf32.tf32.f32 "
        "{%0,%1,%2,%3}, {%4,%5,%6,%7}, {%8,%9}, {%0,%1,%2,%3};"
        : "+f"(c[0]), "+f"(c[1]), "+f"(c[2]), "+f"(c[3])
        : "r"(a[0]), "r"(a[1]), "r"(a[2]), "r"(a[3]), "r"(b[0]), "r"(b[1]));
}

// ---------------------------------------------------------------------------
// 1a) X[bt][c][n]  (zero-padded n)
// ---------------------------------------------------------------------------
__global__ void build_x_kernel(const float* __restrict__ img,
                               const float* __restrict__ tac) {
    int n = blockIdx.x * 256 + threadIdx.x;
    int c = blockIdx.y, bt = blockIdx.z;
    if (n >= NP) return;
    float v = 0.0f;
    if (n < NTOK) {
        int i = n / HF, j = n % HF;
        v = (c < 512)
            ? tac[(((size_t)bt * 512 + c) * 7 + (i / 7)) * 7 + (j / 7)]
            : img[(((size_t)bt * 512 + (c - 512)) * 7 + (i % 7)) * 7 + (j % 7)];
    }
    g_X[((size_t)bt * CF + c) * NP + n] = v;
}

// ---------------------------------------------------------------------------
// 1b) XT[bt][n][c]  (zero rows for n >= NTOK)
// ---------------------------------------------------------------------------
__global__ void build_xt_kernel(const float* __restrict__ img,
                                const float* __restrict__ tac) {
    int c = blockIdx.x * 256 + threadIdx.x;
    int n = blockIdx.y, bt = blockIdx.z;
    if (c >= CF) return;
    float v = 0.0f;
    if (n < NTOK) {
        int i = n / HF, j = n % HF;
        v = (c < 512)
            ? tac[(((size_t)bt * 512 + c) * 7 + (i / 7)) * 7 + (j / 7)]
            : img[(((size_t)bt * 512 + (c - 512)) * 7 + (i % 7)) * 7 + (j % 7)];
    }
    g_XT[((size_t)bt * NP + n) * CF + c] = v;
}

// ---------------------------------------------------------------------------
// 2) row softmax (m < 2401), zero padding columns
// ---------------------------------------------------------------------------
__global__ __launch_bounds__(256)
void softmax_kernel() {
    __shared__ float row[NTOK];
    __shared__ float red[256];
    const int n = blockIdx.x, bt = blockIdx.y;
    float* base = g_ATT + ((size_t)bt * NP + n) * NP;
    const int t = threadIdx.x;

    float mx = -1e30f;
    for (int m = t; m < NTOK; m += 256) { float v = base[m]; row[m] = v; mx = fmaxf(mx, v); }
    red[t] = mx; __syncthreads();
    for (int s = 128; s > 0; s >>= 1) { if (t < s) red[t] = fmaxf(red[t], red[t + s]); __syncthreads(); }
    mx = red[0]; __syncthreads();

    float sum = 0.0f;
    for (int m = t; m < NTOK; m += 256) { float e = __expf(row[m] - mx); row[m] = e; sum += e; }
    red[t] = sum; __syncthreads();
    for (int s = 128; s > 0; s >>= 1) { if (t < s) red[t] += red[t + s]; __syncthreads(); }
    float inv = 1.0f / red[0];

    for (int m = t; m < NTOK; m += 256) base[m] = row[m] * inv;
    for (int m = NTOK + t; m < NP; m += 256) base[m] = 0.0f;
}

// ---------------------------------------------------------------------------
// 3) tf32 mma.sync GEMM: C[M,N] = A[M,K] @ B[N,K]^T, both K-major.
//    Block 128x128, K-chunk 32, 8 warps (2M x 4N), warp tile 64x32.
//    SPLIT=1: plain tf32 (double-buffered)
//    SPLIT=3: 3xTF32 hi/lo split, fp32-grade accuracy (single-buffered)
//    EPI 0: C = acc + bias[row]                 (v projection)
//    EPI 1: C = gamma*acc + X[row][col], col<NTOK  (output)
//    EPI 2: C = acc + bias[col]                 (q/k projection -> QT/KT)
//    EPI 3: C = acc (raw scores)
// ---------------------------------------------------------------------------
#define LDS_S 36
#define MMA_SMEM (4 * 128 * LDS_S * 4)   // 73728 bytes

template <int EPI, int SPLIT>
__global__ __launch_bounds__(256, 1)
void gemm_mma_kernel(const float* __restrict__ A, int lda, size_t strideA,
                     const float* __restrict__ B, int ldb, size_t strideB,
                     int K,
                     const float* __restrict__ bias,
                     const float* __restrict__ gamma,
                     const float* __restrict__ Xres,
                     float* __restrict__ C, int ldc, size_t strideC) {
    extern __shared__ uint32_t sm[];

    const int bt = blockIdx.z;
    const int m0 = blockIdx.x * 128;
    const int n0 = blockIdx.y * 128;
    const float* Ab = A + (size_t)bt * strideA + (size_t)m0 * lda;
    const float* Bb = B + (size_t)bt * strideB + (size_t)n0 * ldb;

    const int t = threadIdx.x;
    const int wid = t >> 5, lane = t & 31;
    const int warp_m = wid & 1, warp_n = wid >> 1;
    const int l4 = lane >> 2, lm = lane & 3;

    // producer mapping: 2 threads per row, 16 floats each
    const int prow = t >> 1;
    const int pcol = (t & 1) * 16;
    const float* aRow = Ab + (size_t)prow * lda + pcol;
    const float* bRow = Bb + (size_t)prow * ldb + pcol;
    const int sOff = prow * LDS_S + pcol;

    float acc[4][4][4];
    #pragma unroll
    for (int mi = 0; mi < 4; mi++)
        #pragma unroll
        for (int ni = 0; ni < 4; ni++)
            #pragma unroll
            for (int r = 0; r < 4; r++) acc[mi][ni][r] = 0.0f;

    const int NCH = K / 32;
    float4 pa[4], pb[4];
    #pragma unroll
    for (int q = 0; q < 4; q++) {
        pa[q] = *reinterpret_cast<const float4*>(aRow + q * 4);
        pb[q] = *reinterpret_cast<const float4*>(bRow + q * 4);
    }

    if (SPLIT == 1) {
        uint32_t* Abuf[2] = { sm,               sm + 2 * 128 * LDS_S };
        uint32_t* Bbuf[2] = { sm + 128 * LDS_S, sm + 3 * 128 * LDS_S };
        #pragma unroll
        for (int q = 0; q < 4; q++) {
            uint4 ua = { f2tf(pa[q].x), f2tf(pa[q].y), f2tf(pa[q].z), f2tf(pa[q].w) };
            uint4 ub = { f2tf(pb[q].x), f2tf(pb[q].y), f2tf(pb[q].z), f2tf(pb[q].w) };
            *reinterpret_cast<uint4*>(&Abuf[0][sOff + q * 4]) = ua;
            *reinterpret_cast<uint4*>(&Bbuf[0][sOff + q * 4]) = ub;
        }
        __syncthreads();

        for (int ch = 0; ch < NCH; ch++) {
            const int buf = ch & 1;
            if (ch + 1 < NCH) {
                const int k1 = (ch + 1) * 32;
                #pragma unroll
                for (int q = 0; q < 4; q++) {
                    pa[q] = *reinterpret_cast<const float4*>(aRow + k1 + q * 4);
                    pb[q] = *reinterpret_cast<const float4*>(bRow + k1 + q * 4);
                }
            }
            const uint32_t* as = Abuf[buf];
            const uint32_t* bs = Bbuf[buf];
            #pragma unroll
            for (int ks = 0; ks < 4; ks++) {
                const int kk = ks * 8;
                uint32_t b[4][2];
                #pragma unroll
                for (int ni = 0; ni < 4; ni++) {
                    int base = (warp_n * 32 + ni * 8 + l4) * LDS_S + kk + lm;
                    b[ni][0] = bs[base];
                    b[ni][1] = bs[base + 4];
                }
                #pragma unroll
                for (int mi = 0; mi < 4; mi++) {
                    int base = (warp_m * 64 + mi * 16 + l4) * LDS_S + kk + lm;
                    uint32_t a[4];
                    a[0] = as[base];
                    a[1] = as[base + 8 * LDS_S];
                    a[2] = as[base + 4];
                    a[3] = as[base + 8 * LDS_S + 4];
                    #pragma unroll
                    for (int ni = 0; ni < 4; ni++) mma_tf32(acc[mi][ni], a, b[ni]);
                }
            }
            if (ch + 1 < NCH) {
                uint32_t* an = Abuf[buf ^ 1];
                uint32_t* bn = Bbuf[buf ^ 1];
                #pragma unroll
                for (int q = 0; q < 4; q++) {
                    uint4 ua = { f2tf(pa[q].x), f2tf(pa[q].y), f2tf(pa[q].z), f2tf(pa[q].w) };
                    uint4 ub = { f2tf(pb[q].x), f2tf(pb[q].y), f2tf(pb[q].z), f2tf(pb[q].w) };
                    *reinterpret_cast<uint4*>(&an[sOff + q * 4]) = ua;
                    *reinterpret_cast<uint4*>(&bn[sOff + q * 4]) = ub;
                }
            }
            __syncthreads();
        }
    } else {
        // SPLIT == 3: hi/lo split, single-buffered
        uint32_t* Ahi = sm;
        uint32_t* Bhi = sm + 128 * LDS_S;
        uint32_t* Alo = sm + 2 * 128 * LDS_S;
        uint32_t* Blo = sm + 3 * 128 * LDS_S;

        for (int ch = 0; ch < NCH; ch++) {
            #pragma unroll
            for (int q = 0; q < 4; q++) {
                uint32_t hx = f2tf(pa[q].x), hy = f2tf(pa[q].y),
                         hz = f2tf(pa[q].z), hw = f2tf(pa[q].w);
                uint4 uh = { hx, hy, hz, hw };
                uint4 ul = { f2tf(pa[q].x - __uint_as_float(hx)),
                             f2tf(pa[q].y - __uint_as_float(hy)),
                             f2tf(pa[q].z - __uint_as_float(hz)),
                             f2tf(pa[q].w - __uint_as_float(hw)) };
                *reinterpret_cast<uint4*>(&Ahi[sOff + q * 4]) = uh;
                *reinterpret_cast<uint4*>(&Alo[sOff + q * 4]) = ul;
                hx = f2tf(pb[q].x); hy = f2tf(pb[q].y);
                hz = f2tf(pb[q].z); hw = f2tf(pb[q].w);
                uint4 vh = { hx, hy, hz, hw };
                uint4 vl = { f2tf(pb[q].x - __uint_as_float(hx)),
                             f2tf(pb[q].y - __uint_as_float(hy)),
                             f2tf(pb[q].z - __uint_as_float(hz)),
                             f2tf(pb[q].w - __uint_as_float(hw)) };
                *reinterpret_cast<uint4*>(&Bhi[sOff + q * 4]) = vh;
                *reinterpret_cast<uint4*>(&Blo[sOff + q * 4]) = vl;
            }
            __syncthreads();
            if (ch + 1 < NCH) {
                const int k1 = (ch + 1) * 32;
                #pragma unroll
                for (int q = 0; q < 4; q++) {
                    pa[q] = *reinterpret_cast<const float4*>(aRow + k1 + q * 4);
                    pb[q] = *reinterpret_cast<const float4*>(bRow + k1 + q * 4);
                }
            }
            #pragma unroll
            for (int ks = 0; ks < 4; ks++) {
                const int kk = ks * 8;
                uint32_t bh[4][2], bl[4][2];
                #pragma unroll
                for (int ni = 0; ni < 4; ni++) {
                    int base = (warp_n * 32 + ni * 8 + l4) * LDS_S + kk + lm;
                    bh[ni][0] = Bhi[base];  bh[ni][1] = Bhi[base + 4];
                    bl[ni][0] = Blo[base];  bl[ni][1] = Blo[base + 4];
                }
                #pragma unroll
                for (int mi = 0; mi < 4; mi++) {
                    int base = (warp_m * 64 + mi * 16 + l4) * LDS_S + kk + lm;
                    uint32_t ah[4], al[4];
                    ah[0] = Ahi[base];               al[0] = Alo[base];
                    ah[1] = Ahi[base + 8 * LDS_S];   al[1] = Alo[base + 8 * LDS_S];
                    ah[2] = Ahi[base + 4];           al[2] = Alo[base + 4];
                    ah[3] = Ahi[base + 8 * LDS_S + 4]; al[3] = Alo[base + 8 * LDS_S + 4];
                    #pragma unroll
                    for (int ni = 0; ni < 4; ni++) {
                        mma_tf32(acc[mi][ni], ah, bl[ni]);
                        mma_tf32(acc[mi][ni], al, bh[ni]);
                        mma_tf32(acc[mi][ni], ah, bh[ni]);
                    }
                }
            }
            __syncthreads();
        }
    }

    // ------------------------- epilogues -------------------------
    float* Cb = C + (size_t)bt * strideC;
    if (EPI == 0) {
        #pragma unroll
        for (int mi = 0; mi < 4; mi++) {
            const int gr = m0 + warp_m * 64 + mi * 16 + l4;
            const float bv0 = bias[gr], bv8 = bias[gr + 8];
            #pragma unroll
            for (int ni = 0; ni < 4; ni++) {
                const int gc = n0 + warp_n * 32 + ni * 8 + lm * 2;
                float2 o0 = { acc[mi][ni][0] + bv0, acc[mi][ni][1] + bv0 };
                float2 o1 = { acc[mi][ni][2] + bv8, acc[mi][ni][3] + bv8 };
                *reinterpret_cast<float2*>(&Cb[(size_t)gr * ldc + gc]) = o0;
                *reinterpret_cast<float2*>(&Cb[(size_t)(gr + 8) * ldc + gc]) = o1;
            }
        }
    } else if (EPI == 1) {
        const float g = __ldg(gamma);
        const float* Xb = Xres + (size_t)bt * CF * NP;
        #pragma unroll
        for (int mi = 0; mi < 4; mi++) {
            const int gr = m0 + warp_m * 64 + mi * 16 + l4;
            #pragma unroll
            for (int ni = 0; ni < 4; ni++) {
                const int gc = n0 + warp_n * 32 + ni * 8 + lm * 2;
                if (gc < NTOK)
                    Cb[(size_t)gr * ldc + gc] = g * acc[mi][ni][0] + Xb[(size_t)gr * NP + gc];
                if (gc + 1 < NTOK)
                    Cb[(size_t)gr * ldc + gc + 1] = g * acc[mi][ni][1] + Xb[(size_t)gr * NP + gc + 1];
                if (gc < NTOK)
                    Cb[(size_t)(gr + 8) * ldc + gc] = g * acc[mi][ni][2] + Xb[(size_t)(gr + 8) * NP + gc];
                if (gc + 1 < NTOK)
                    Cb[(size_t)(gr + 8) * ldc + gc + 1] = g * acc[mi][ni][3] + Xb[(size_t)(gr + 8) * NP + gc + 1];
            }
        }
    } else if (EPI == 2) {
        #pragma unroll
        for (int mi = 0; mi < 4; mi++) {
            const int gr = m0 + warp_m * 64 + mi * 16 + l4;
            #pragma unroll
            for (int ni = 0; ni < 4; ni++) {
                const int gc = n0 + warp_n * 32 + ni * 8 + lm * 2;
                const float b0 = bias[gc], b1 = bias[gc + 1];
                float2 o0 = { acc[mi][ni][0] + b0, acc[mi][ni][1] + b1 };
                float2 o1 = { acc[mi][ni][2] + b0, acc[mi][ni][3] + b1 };
                *reinterpret_cast<float2*>(&Cb[(size_t)gr * ldc + gc]) = o0;
                *reinterpret_cast<float2*>(&Cb[(size_t)(gr + 8) * ldc + gc]) = o1;
            }
        }
    } else {
        #pragma unroll
        for (int mi = 0; mi < 4; mi++) {
            const int gr = m0 + warp_m * 64 + mi * 16 + l4;
            #pragma unroll
            for (int ni = 0; ni < 4; ni++) {
                const int gc = n0 + warp_n * 32 + ni * 8 + lm * 2;
                float2 o0 = { acc[mi][ni][0], acc[mi][ni][1] };
                float2 o1 = { acc[mi][ni][2], acc[mi][ni][3] };
                *reinterpret_cast<float2*>(&Cb[(size_t)gr * ldc + gc]) = o0;
                *reinterpret_cast<float2*>(&Cb[(size_t)(gr + 8) * ldc + gc]) = o1;
            }
        }
    }
}

// ---------------------------------------------------------------------------
// Launch
// ---------------------------------------------------------------------------
extern "C" void kernel_launch(void* const* d_in, const int* in_sizes, int n_in,
                              void* d_out, int out_size) {
    const float* img   = (const float*)d_in[0];
    const float* tac   = (const float*)d_in[1];
    const float* Wq    = (const float*)d_in[2];
    const float* bq    = (const float*)d_in[3];
    const float* Wk    = (const float*)d_in[4];
    const float* bk    = (const float*)d_in[5];
    const float* Wv    = (const float*)d_in[6];
    const float* bv    = (const float*)d_in[7];
    const float* gamma = (const float*)d_in[8];
    float* out = (float*)d_out;

    float* gX;  cudaGetSymbolAddress((void**)&gX,  g_X);
    float* gXT; cudaGetSymbolAddress((void**)&gXT, g_XT);
    float* gQT; cudaGetSymbolAddress((void**)&gQT, g_QT);
    float* gKT; cudaGetSymbolAddress((void**)&gKT, g_KT);
    float* gV;  cudaGetSymbolAddress((void**)&gV,  g_V);
    float* gA;  cudaGetSymbolAddress((void**)&gA,  g_ATT);

    cudaFuncSetAttribute(gemm_mma_kernel<0,1>, cudaFuncAttributeMaxDynamicSharedMemorySize, MMA_SMEM);
    cudaFuncSetAttribute(gemm_mma_kernel<1,1>, cudaFuncAttributeMaxDynamicSharedMemorySize, MMA_SMEM);
    cudaFuncSetAttribute(gemm_mma_kernel<2,3>, cudaFuncAttributeMaxDynamicSharedMemorySize, MMA_SMEM);
    cudaFuncSetAttribute(gemm_mma_kernel<3,3>, cudaFuncAttributeMaxDynamicSharedMemorySize, MMA_SMEM);

    // 1) fused feature maps
    build_x_kernel <<<dim3((NP + 255) / 256, CF, BT), 256>>>(img, tac);
    build_xt_kernel<<<dim3(CF / 256, NP, BT), 256>>>(img, tac);

    // 2) q, k projections (3xTF32): QT[n][o] = XT[n][:] @ Wq^T + bq
    gemm_mma_kernel<2,3><<<dim3(NP / 128, 1, BT), 256, MMA_SMEM>>>(
        gXT, CF, (size_t)NP * CF,
        Wq, CF, 0,
        CF, bq, nullptr, nullptr,
        gQT, CQ, (size_t)NP * CQ);
    gemm_mma_kernel<2,3><<<dim3(NP / 128, 1, BT), 256, MMA_SMEM>>>(
        gXT, CF, (size_t)NP * CF,
        Wk, CF, 0,
        CF, bk, nullptr, nullptr,
        gKT, CQ, (size_t)NP * CQ);

    // 3) v projection (tf32): V[c][n] = Wv @ XT^T + bv
    gemm_mma_kernel<0,1><<<dim3(CF / 128, NP / 128, BT), 256, MMA_SMEM>>>(
        Wv, CF, 0,
        gXT, CF, (size_t)NP * CF,
        CF, bv, nullptr, nullptr,
        gV, NP, (size_t)CF * NP);

    // 4) attention scores (3xTF32): S[n][m] = QT[n][:] @ KT[m][:]^T
    gemm_mma_kernel<3,3><<<dim3(NP / 128, NP / 128, BT), 256, MMA_SMEM>>>(
        gQT, CQ, (size_t)NP * CQ,
        gKT, CQ, (size_t)NP * CQ,
        CQ, nullptr, nullptr, nullptr,
        gA, NP, (size_t)NP * NP);

    // 5) softmax
    softmax_kernel<<<dim3(NTOK, BT), 256>>>();

    // 6) out = gamma * (V @ P^T) + X (tf32)
    gemm_mma_kernel<1,1><<<dim3(CF / 128, NP / 128, BT), 256, MMA_SMEM>>>(
        gV, NP, (size_t)CF * NP,
        gA, NP, (size_t)NP * NP,
        NP, nullptr, gamma, gX,
        out, NTOK, (size_t)CF * NTOK);
}